// round 1
// baseline (speedup 1.0000x reference)
#include <cuda_runtime.h>
#include <math.h>

// Problem constants
#define BN 16
#define NN 1024
#define UU 64
#define KDIM 128        // 2U
#define MAXD 128        // max neighbor degree (avg ~33, binomial tail safe)
#define ALPHA 0.2f

// ---------------- scratch (device globals; no allocation allowed) ----------------
__device__ float g_h1[BN * NN * 128];     // layer-1 features h = X1 @ W1
__device__ float g_ssrc1[BN * NN];
__device__ float g_sdst1[BN * NN];
__device__ float g_z[BN * NN * UU];       // gate z
__device__ float g_rs[BN * NN * UU];      // r * state
__device__ float g_h2[BN * NN * UU];      // layer-2 features
__device__ float g_ssrc2[BN * NN];
__device__ float g_sdst2[BN * NN];
__device__ int   g_nbr[NN * MAXD];
__device__ int   g_cnt[NN];

// ---------------- neighbor list build ----------------
__global__ void build_nbr_kernel(const float* __restrict__ adj) {
    __shared__ int c;
    int i = blockIdx.x;
    if (threadIdx.x == 0) c = 0;
    __syncthreads();
    for (int j = threadIdx.x; j < NN; j += blockDim.x) {
        if (adj[i * NN + j] > 0.0f) {
            int p = atomicAdd(&c, 1);
            if (p < MAXD) g_nbr[i * MAXD + p] = j;
        }
    }
    __syncthreads();
    if (threadIdx.x == 0) g_cnt[i] = (c < MAXD) ? c : MAXD;
}

// ---------------- fused-concat GEMM: H[row, c] = sum_k cat(X,S)[row,k] * W[k,c] ----------------
// rows = BN*NN = 16384, K = 128, F = 128 (layer1) or 64 (layer2)
template <int F, int LAYER>
__global__ void gemm_cat_kernel(const float* __restrict__ X,
                                const float* __restrict__ S,   // state (L1) — ignored for L2
                                const float* __restrict__ W) {
    constexpr int RT = 64;   // rows per block
    constexpr int KC = 32;   // K chunk
    constexpr int CC = F / 16;

    __shared__ float Xs[KC][RT + 1];
    __shared__ float Ws[KC][F + 1];

    const float* Ssrc = (LAYER == 1) ? S : g_rs;
    float*       H    = (LAYER == 1) ? g_h1 : g_h2;

    int tx = threadIdx.x & 15;
    int ty = threadIdx.x >> 4;
    int row0 = blockIdx.x * RT;

    float acc[4][CC];
#pragma unroll
    for (int r = 0; r < 4; r++)
#pragma unroll
        for (int c = 0; c < CC; c++) acc[r][c] = 0.0f;

    for (int k0 = 0; k0 < KDIM; k0 += KC) {
        // stage X tile (concat on the fly)
        for (int idx = threadIdx.x; idx < RT * KC; idx += 256) {
            int r = idx / KC, k = idx % KC;
            int row = row0 + r;
            int kk = k0 + k;
            float v = (kk < UU) ? X[row * UU + kk] : Ssrc[row * UU + kk - UU];
            Xs[k][r] = v;
        }
        // stage W tile
        for (int idx = threadIdx.x; idx < KC * F; idx += 256) {
            int k = idx / F, c = idx % F;
            Ws[k][c] = W[(k0 + k) * F + c];
        }
        __syncthreads();
#pragma unroll
        for (int k = 0; k < KC; k++) {
            float a[4], bb[CC];
#pragma unroll
            for (int r = 0; r < 4; r++) a[r] = Xs[k][ty + 16 * r];
#pragma unroll
            for (int c = 0; c < CC; c++) bb[c] = Ws[k][tx + 16 * c];
#pragma unroll
            for (int r = 0; r < 4; r++)
#pragma unroll
                for (int c = 0; c < CC; c++) acc[r][c] = fmaf(a[r], bb[c], acc[r][c]);
        }
        __syncthreads();
    }
#pragma unroll
    for (int r = 0; r < 4; r++) {
        int row = row0 + ty + 16 * r;
#pragma unroll
        for (int c = 0; c < CC; c++) H[row * F + tx + 16 * c] = acc[r][c];
    }
}

// ---------------- attention scores: s_src/s_dst = h . a-halves ----------------
template <int F, int LAYER>
__global__ void scores_kernel(const float* __restrict__ a) {
    const float* H  = (LAYER == 1) ? g_h1 : g_h2;
    float* ssrc     = (LAYER == 1) ? g_ssrc1 : g_ssrc2;
    float* sdst     = (LAYER == 1) ? g_sdst1 : g_sdst2;
    int row  = blockIdx.x * (blockDim.x >> 5) + (threadIdx.x >> 5);
    int lane = threadIdx.x & 31;
    if (row >= BN * NN) return;
    float s1 = 0.0f, s2 = 0.0f;
#pragma unroll
    for (int c = lane; c < F; c += 32) {
        float h = H[row * F + c];
        s1 = fmaf(h, a[c], s1);
        s2 = fmaf(h, a[F + c], s2);
    }
#pragma unroll
    for (int off = 16; off > 0; off >>= 1) {
        s1 += __shfl_down_sync(0xffffffffu, s1, off);
        s2 += __shfl_down_sync(0xffffffffu, s2, off);
    }
    if (lane == 0) { ssrc[row] = s1; sdst[row] = s2; }
}

// ---------------- masked-softmax attention + aggregate + epilogue ----------------
// block = (i over x, b over y), F threads; each thread owns one output feature.
template <int F, int LAYER>
__global__ void attn_kernel(const float* __restrict__ state, float* __restrict__ out) {
    const float* H    = (LAYER == 1) ? g_h1 : g_h2;
    const float* ssrc = (LAYER == 1) ? g_ssrc1 : g_ssrc2;
    const float* sdst = (LAYER == 1) ? g_sdst1 : g_sdst2;

    int i = blockIdx.x;
    int b = blockIdx.y;
    int tid = threadIdx.x;

    __shared__ float sw[MAXD];
    __shared__ int   sj[MAXD];

    int cnt = g_cnt[i];
    float si = ssrc[b * NN + i];

    for (int k = tid; k < cnt; k += F) {
        int j = g_nbr[i * MAXD + k];
        sj[k] = j;
        float e = si + sdst[b * NN + j];
        sw[k] = (e > 0.0f) ? e : ALPHA * e;
    }
    __syncthreads();

    float m = -3.0e38f;
    for (int k = 0; k < cnt; k++) m = fmaxf(m, sw[k]);   // broadcast shared reads
    __syncthreads();
    for (int k = tid; k < cnt; k += F) sw[k] = __expf(sw[k] - m);
    __syncthreads();
    float ssum = 0.0f;
    for (int k = 0; k < cnt; k++) ssum += sw[k];
    float inv = 1.0f / ssum;

    float acc = 0.0f;
#pragma unroll 4
    for (int k = 0; k < cnt; k++)
        acc = fmaf(sw[k], H[(b * NN + sj[k]) * F + tid], acc);
    acc *= inv;

    int base = (b * NN + i) * UU;
    if (LAYER == 1) {
        float g = 1.0f / (1.0f + __expf(-acc));
        if (tid < UU) {
            // r gate -> r*state
            g_rs[base + tid] = g * state[base + tid];
        } else {
            g_z[base + tid - UU] = g;
        }
    } else {
        float ht = tanhf(acc);
        float z = g_z[base + tid];
        out[base + tid] = fmaf(z, state[base + tid], (1.0f - z) * ht);
    }
}

// ---------------- launch ----------------
extern "C" void kernel_launch(void* const* d_in, const int* in_sizes, int n_in,
                              void* d_out, int out_size) {
    const float* X     = (const float*)d_in[0];
    const float* state = (const float*)d_in[1];
    const float* adj   = (const float*)d_in[2];
    const float* W1    = (const float*)d_in[3];
    const float* a1    = (const float*)d_in[4];
    const float* W2    = (const float*)d_in[5];
    const float* a2    = (const float*)d_in[6];
    float* out = (float*)d_out;

    // 1) neighbor lists
    build_nbr_kernel<<<NN, 128>>>(adj);

    // 2) layer 1: h1 = [X||state] @ W1
    gemm_cat_kernel<128, 1><<<(BN * NN) / 64, 256>>>(X, state, W1);

    // 3) scores layer 1
    scores_kernel<128, 1><<<(BN * NN) / 8, 256>>>(a1);

    // 4) attention layer 1 (+ sigmoid, r*state, z)
    attn_kernel<128, 1><<<dim3(NN, BN), 128>>>(state, out);

    // 5) layer 2: h2 = [X||r*state] @ W2
    gemm_cat_kernel<64, 2><<<(BN * NN) / 64, 256>>>(X, state, W2);

    // 6) scores layer 2
    scores_kernel<64, 2><<<(BN * NN) / 8, 256>>>(a2);

    // 7) attention layer 2 (+ tanh + GRU gate -> out)
    attn_kernel<64, 2><<<dim3(NN, BN), 64>>>(state, out);
}

// round 2
// speedup vs baseline: 1.0182x; 1.0182x over previous
#include <cuda_runtime.h>
#include <math.h>
#include <float.h>

// Problem constants
#define BN 16
#define NN 1024
#define UU 64
#define KDIM 128        // 2U
#define MAXD 128        // max neighbor degree (avg ~33, binomial tail safe)
#define ALPHA 0.2f

// ---------------- scratch (device globals; no allocation allowed) ----------------
__device__ float g_h1[BN * NN * 128];     // layer-1 features h = X1 @ W1
__device__ float g_ssrc1[BN * NN];
__device__ float g_sdst1[BN * NN];
__device__ float g_z[BN * NN * UU];       // gate z
__device__ float g_rs[BN * NN * UU];      // r * state
__device__ float g_h2[BN * NN * UU];      // layer-2 features
__device__ float g_ssrc2[BN * NN];
__device__ float g_sdst2[BN * NN];
__device__ int   g_nbr[NN * MAXD];
__device__ int   g_cnt[NN];

// ---------------- neighbor list build (deterministic, ascending j) ----------------
__global__ void build_nbr_kernel(const float* __restrict__ adj) {
    int i = blockIdx.x;
    int tid = threadIdx.x;             // 128 threads
    int lane = tid & 31, wid = tid >> 5;
    __shared__ int wcnt[4];
    __shared__ int sbase;
    if (tid == 0) sbase = 0;
    __syncthreads();
    for (int j0 = 0; j0 < NN; j0 += 128) {
        int j = j0 + tid;
        bool p = adj[i * NN + j] > 0.0f;
        unsigned ball = __ballot_sync(0xffffffffu, p);
        if (lane == 0) wcnt[wid] = __popc(ball);
        __syncthreads();
        int off = sbase;
#pragma unroll
        for (int w = 0; w < 4; w++) if (w < wid) off += wcnt[w];
        int tot = wcnt[0] + wcnt[1] + wcnt[2] + wcnt[3];
        if (p) {
            int pos = off + __popc(ball & ((1u << lane) - 1u));
            if (pos < MAXD) g_nbr[i * MAXD + pos] = j;
        }
        __syncthreads();
        if (tid == 0) sbase += tot;
    }
    __syncthreads();
    if (tid == 0) g_cnt[i] = (sbase < MAXD) ? sbase : MAXD;
}

// ---------------- fused-concat GEMM: H[row, c] = sum_k cat(X,S)[row,k] * W[k,c] ----------------
template <int F, int LAYER>
__global__ void gemm_cat_kernel(const float* __restrict__ X,
                                const float* __restrict__ S,
                                const float* __restrict__ W) {
    constexpr int RT = 64;
    constexpr int KC = 32;
    constexpr int CC = F / 16;

    __shared__ float Xs[KC][RT + 1];
    __shared__ float Ws[KC][F + 1];

    const float* Ssrc = (LAYER == 1) ? S : g_rs;
    float*       H    = (LAYER == 1) ? g_h1 : g_h2;

    int tx = threadIdx.x & 15;
    int ty = threadIdx.x >> 4;
    int row0 = blockIdx.x * RT;

    float acc[4][CC];
#pragma unroll
    for (int r = 0; r < 4; r++)
#pragma unroll
        for (int c = 0; c < CC; c++) acc[r][c] = 0.0f;

    for (int k0 = 0; k0 < KDIM; k0 += KC) {
        for (int idx = threadIdx.x; idx < RT * KC; idx += 256) {
            int r = idx / KC, k = idx % KC;
            int row = row0 + r;
            int kk = k0 + k;
            float v = (kk < UU) ? X[row * UU + kk] : Ssrc[row * UU + kk - UU];
            Xs[k][r] = v;
        }
        for (int idx = threadIdx.x; idx < KC * F; idx += 256) {
            int k = idx / F, c = idx % F;
            Ws[k][c] = W[(k0 + k) * F + c];
        }
        __syncthreads();
#pragma unroll
        for (int k = 0; k < KC; k++) {
            float a[4], bb[CC];
#pragma unroll
            for (int r = 0; r < 4; r++) a[r] = Xs[k][ty + 16 * r];
#pragma unroll
            for (int c = 0; c < CC; c++) bb[c] = Ws[k][tx + 16 * c];
#pragma unroll
            for (int r = 0; r < 4; r++)
#pragma unroll
                for (int c = 0; c < CC; c++) acc[r][c] = fmaf(a[r], bb[c], acc[r][c]);
        }
        __syncthreads();
    }
#pragma unroll
    for (int r = 0; r < 4; r++) {
        int row = row0 + ty + 16 * r;
#pragma unroll
        for (int c = 0; c < CC; c++) H[row * F + tx + 16 * c] = acc[r][c];
    }
}

// ---------------- attention scores: s_src/s_dst = h . a-halves ----------------
template <int F, int LAYER>
__global__ void scores_kernel(const float* __restrict__ a) {
    const float* H  = (LAYER == 1) ? g_h1 : g_h2;
    float* ssrc     = (LAYER == 1) ? g_ssrc1 : g_ssrc2;
    float* sdst     = (LAYER == 1) ? g_sdst1 : g_sdst2;
    int row  = blockIdx.x * (blockDim.x >> 5) + (threadIdx.x >> 5);
    int lane = threadIdx.x & 31;
    if (row >= BN * NN) return;
    float s1 = 0.0f, s2 = 0.0f;
#pragma unroll
    for (int c = lane; c < F; c += 32) {
        float h = H[row * F + c];
        s1 = fmaf(h, a[c], s1);
        s2 = fmaf(h, a[F + c], s2);
    }
#pragma unroll
    for (int off = 16; off > 0; off >>= 1) {
        s1 += __shfl_down_sync(0xffffffffu, s1, off);
        s2 += __shfl_down_sync(0xffffffffu, s2, off);
    }
    if (lane == 0) { ssrc[row] = s1; sdst[row] = s2; }
}

// ---------------- masked-softmax attention + aggregate + epilogue ----------------
// Block = (i, batch-group of BPB). blockDim = F*BPB.
// Phase 1: warp w (w < BPB) computes softmax for batch b0+w in registers (warp reduce).
// Phase 2: thread (bb, f) gathers H rows with unroll-4 MLP.
template <int F, int BPB, int LAYER>
__global__ void attn_kernel(const float* __restrict__ state, float* __restrict__ out) {
    const float* H    = (LAYER == 1) ? g_h1 : g_h2;
    const float* ssrc = (LAYER == 1) ? g_ssrc1 : g_ssrc2;
    const float* sdst = (LAYER == 1) ? g_sdst1 : g_sdst2;

    int i  = blockIdx.x;
    int b0 = blockIdx.y * BPB;
    int tid  = threadIdx.x;
    int lane = tid & 31;
    int wid  = tid >> 5;

    __shared__ int   sj[MAXD];
    __shared__ float sw[BPB][MAXD];
    __shared__ int   scnt;

    if (tid == 0) scnt = g_cnt[i];
    for (int k = tid; k < MAXD; k += F * BPB) sj[k] = g_nbr[i * MAXD + k];
    __syncthreads();
    int cnt = scnt;

    // ---- phase 1: per-warp softmax for one batch ----
    if (wid < BPB) {
        int b = b0 + wid;
        float si = ssrc[b * NN + i];
        const float* sd = sdst + b * NN;
        float ee[MAXD / 32];
        float m = -FLT_MAX;
#pragma unroll
        for (int u = 0; u < MAXD / 32; u++) {
            int k = lane + 32 * u;
            float e = -FLT_MAX;
            if (k < cnt) {
                float v = si + sd[sj[k]];
                e = (v > 0.0f) ? v : ALPHA * v;
            }
            ee[u] = e;
            m = fmaxf(m, e);
        }
#pragma unroll
        for (int off = 16; off > 0; off >>= 1)
            m = fmaxf(m, __shfl_xor_sync(0xffffffffu, m, off));
        float s = 0.0f;
#pragma unroll
        for (int u = 0; u < MAXD / 32; u++) {
            int k = lane + 32 * u;
            if (k < cnt) {
                float w = __expf(ee[u] - m);
                ee[u] = w;
                s += w;
            }
        }
#pragma unroll
        for (int off = 16; off > 0; off >>= 1)
            s += __shfl_xor_sync(0xffffffffu, s, off);
        float inv = 1.0f / s;
#pragma unroll
        for (int u = 0; u < MAXD / 32; u++) {
            int k = lane + 32 * u;
            if (k < cnt) sw[wid][k] = ee[u] * inv;
        }
    }
    __syncthreads();

    // ---- phase 2: gather-aggregate with MLP ----
    int bb = tid / F;
    int f  = tid - bb * F;
    int b  = b0 + bb;
    const float* Hb = H + (size_t)(b * NN) * F + f;
    const float* wrow = sw[bb];

    float acc0 = 0.0f, acc1 = 0.0f;
    int k = 0;
    for (; k + 4 <= cnt; k += 4) {
        int j0 = sj[k], j1 = sj[k + 1], j2 = sj[k + 2], j3 = sj[k + 3];
        float w0 = wrow[k], w1 = wrow[k + 1], w2 = wrow[k + 2], w3 = wrow[k + 3];
        float h0 = Hb[j0 * F];
        float h1 = Hb[j1 * F];
        float h2 = Hb[j2 * F];
        float h3 = Hb[j3 * F];
        acc0 = fmaf(w0, h0, acc0);
        acc1 = fmaf(w1, h1, acc1);
        acc0 = fmaf(w2, h2, acc0);
        acc1 = fmaf(w3, h3, acc1);
    }
    for (; k < cnt; k++) acc0 = fmaf(wrow[k], Hb[sj[k] * F], acc0);
    float acc = acc0 + acc1;

    int base = (b * NN + i) * UU;
    if (LAYER == 1) {
        float g = 1.0f / (1.0f + __expf(-acc));
        if (f < UU) {
            g_rs[base + f] = g * state[base + f];
        } else {
            g_z[base + f - UU] = g;
        }
    } else {
        float ht = tanhf(acc);
        float z = g_z[base + f];
        out[base + f] = fmaf(z, state[base + f], (1.0f - z) * ht);
    }
}

// ---------------- launch ----------------
extern "C" void kernel_launch(void* const* d_in, const int* in_sizes, int n_in,
                              void* d_out, int out_size) {
    const float* X     = (const float*)d_in[0];
    const float* state = (const float*)d_in[1];
    const float* adj   = (const float*)d_in[2];
    const float* W1    = (const float*)d_in[3];
    const float* a1    = (const float*)d_in[4];
    const float* W2    = (const float*)d_in[5];
    const float* a2    = (const float*)d_in[6];
    float* out = (float*)d_out;

    // 1) neighbor lists (deterministic)
    build_nbr_kernel<<<NN, 128>>>(adj);

    // 2) layer 1: h1 = [X||state] @ W1
    gemm_cat_kernel<128, 1><<<(BN * NN) / 64, 256>>>(X, state, W1);

    // 3) scores layer 1
    scores_kernel<128, 1><<<(BN * NN) / 8, 256>>>(a1);

    // 4) attention layer 1 (+ sigmoid, r*state, z) — 2 batches/block
    attn_kernel<128, 2, 1><<<dim3(NN, BN / 2), 256>>>(state, out);

    // 5) layer 2: h2 = [X||r*state] @ W2
    gemm_cat_kernel<64, 2><<<(BN * NN) / 64, 256>>>(X, state, W2);

    // 6) scores layer 2
    scores_kernel<64, 2><<<(BN * NN) / 8, 256>>>(a2);

    // 7) attention layer 2 (+ tanh + GRU gate -> out) — 4 batches/block
    attn_kernel<64, 4, 2><<<dim3(NN, BN / 4), 256>>>(state, out);
}

// round 3
// speedup vs baseline: 1.4557x; 1.4297x over previous
#include <cuda_runtime.h>
#include <cuda_fp16.h>
#include <math.h>
#include <float.h>

// Problem constants
#define BN 16
#define NN 1024
#define UU 64
#define KDIM 128        // 2U
#define MAXD 128        // max neighbor degree (avg ~33)
#define ALPHA 0.2f

// ---------------- scratch (device globals; no allocation allowed) ----------------
__device__ __half g_h1[BN * NN * 128];    // layer-1 features (fp16 gather copy)
__device__ __half g_h2[BN * NN * UU];     // layer-2 features
__device__ float g_ssrc1[BN * NN];
__device__ float g_sdst1[BN * NN];
__device__ float g_ssrc2[BN * NN];
__device__ float g_sdst2[BN * NN];
__device__ float g_z[BN * NN * UU];       // gate z
__device__ float g_rs[BN * NN * UU];      // r * state
__device__ int   g_nbr[NN * MAXD];
__device__ int   g_cnt[NN];

// ---------------- neighbor list build (deterministic, ascending j) ----------------
__global__ void build_nbr_kernel(const float* __restrict__ adj) {
    int i = blockIdx.x;
    int tid = threadIdx.x;             // 128 threads
    int lane = tid & 31, wid = tid >> 5;
    __shared__ int wcnt[4];
    __shared__ int sbase;
    if (tid == 0) sbase = 0;
    __syncthreads();
    for (int j0 = 0; j0 < NN; j0 += 128) {
        int j = j0 + tid;
        bool p = adj[i * NN + j] > 0.0f;
        unsigned ball = __ballot_sync(0xffffffffu, p);
        if (lane == 0) wcnt[wid] = __popc(ball);
        __syncthreads();
        int off = sbase;
#pragma unroll
        for (int w = 0; w < 4; w++) if (w < wid) off += wcnt[w];
        int tot = wcnt[0] + wcnt[1] + wcnt[2] + wcnt[3];
        if (p) {
            int pos = off + __popc(ball & ((1u << lane) - 1u));
            if (pos < MAXD) g_nbr[i * MAXD + pos] = j;
        }
        __syncthreads();
        if (tid == 0) sbase += tot;
    }
    __syncthreads();
    if (tid == 0) g_cnt[i] = (sbase < MAXD) ? sbase : MAXD;
}

// ---------------- fused-concat GEMM + fp16 store + fused attention scores ----------------
// H[row,c] = sum_k cat(X,S)[row,k] * W[k,c];  s_src/s_dst = H[row,:] . a-halves (fp32)
template <int F, int LAYER>
__global__ void gemm_cat_kernel(const float* __restrict__ X,
                                const float* __restrict__ S,
                                const float* __restrict__ W,
                                const float* __restrict__ a) {
    constexpr int RT = 64;
    constexpr int KC = 32;
    constexpr int CC = F / 16;

    __shared__ float Xs[KC][RT + 1];
    __shared__ float Ws[KC][F + 1];

    const float* Ssrc = (LAYER == 1) ? S : g_rs;
    __half*      H    = (LAYER == 1) ? g_h1 : g_h2;
    float*       ssrc = (LAYER == 1) ? g_ssrc1 : g_ssrc2;
    float*       sdst = (LAYER == 1) ? g_sdst1 : g_sdst2;

    int tx = threadIdx.x & 15;
    int ty = threadIdx.x >> 4;
    int row0 = blockIdx.x * RT;

    float acc[4][CC];
#pragma unroll
    for (int r = 0; r < 4; r++)
#pragma unroll
        for (int c = 0; c < CC; c++) acc[r][c] = 0.0f;

    for (int k0 = 0; k0 < KDIM; k0 += KC) {
        for (int idx = threadIdx.x; idx < RT * KC; idx += 256) {
            int r = idx / KC, k = idx % KC;
            int row = row0 + r;
            int kk = k0 + k;
            float v = (kk < UU) ? X[row * UU + kk] : Ssrc[row * UU + kk - UU];
            Xs[k][r] = v;
        }
        for (int idx = threadIdx.x; idx < KC * F; idx += 256) {
            int k = idx / F, c = idx % F;
            Ws[k][c] = W[(k0 + k) * F + c];
        }
        __syncthreads();
#pragma unroll
        for (int k = 0; k < KC; k++) {
            float av[4], bb[CC];
#pragma unroll
            for (int r = 0; r < 4; r++) av[r] = Xs[k][ty + 16 * r];
#pragma unroll
            for (int c = 0; c < CC; c++) bb[c] = Ws[k][tx + 16 * c];
#pragma unroll
            for (int r = 0; r < 4; r++)
#pragma unroll
                for (int c = 0; c < CC; c++) acc[r][c] = fmaf(av[r], bb[c], acc[r][c]);
        }
        __syncthreads();
    }

    // epilogue: fp16 store + fused scores
#pragma unroll
    for (int r = 0; r < 4; r++) {
        int row = row0 + ty + 16 * r;
        float s1 = 0.0f, s2 = 0.0f;
#pragma unroll
        for (int c = 0; c < CC; c++) {
            int col = tx + 16 * c;
            H[(size_t)row * F + col] = __float2half(acc[r][c]);
            s1 = fmaf(acc[r][c], a[col], s1);
            s2 = fmaf(acc[r][c], a[F + col], s2);
        }
        // reduce across the 16 tx lanes (within half-warp)
#pragma unroll
        for (int off = 8; off > 0; off >>= 1) {
            s1 += __shfl_xor_sync(0xffffffffu, s1, off);
            s2 += __shfl_xor_sync(0xffffffffu, s2, off);
        }
        if (tx == 0) { ssrc[row] = s1; sdst[row] = s2; }
    }
}

// ---------------- masked-softmax attention + fp16 gather + epilogue ----------------
// Block = (i, batch-group BPB). blockDim = BPB * F/2 (each thread: one __half2 pair).
template <int F, int BPB, int LAYER>
__global__ void attn_kernel(const float* __restrict__ state, float* __restrict__ out) {
    constexpr int F2 = F / 2;
    const __half* H   = (LAYER == 1) ? g_h1 : g_h2;
    const float* ssrc = (LAYER == 1) ? g_ssrc1 : g_ssrc2;
    const float* sdst = (LAYER == 1) ? g_sdst1 : g_sdst2;

    int i  = blockIdx.x;
    int b0 = blockIdx.y * BPB;
    int tid  = threadIdx.x;
    int lane = tid & 31;
    int wid  = tid >> 5;

    __shared__ int   sj[MAXD];
    __shared__ float sw[BPB][MAXD];
    __shared__ int   scnt;

    if (tid == 0) scnt = g_cnt[i];
    for (int k = tid; k < MAXD; k += BPB * F2) sj[k] = g_nbr[i * MAXD + k];
    __syncthreads();
    int cnt = scnt;

    // ---- phase 1: per-warp softmax for one batch (pre-normalized weights) ----
    if (wid < BPB) {
        int b = b0 + wid;
        float si = ssrc[b * NN + i];
        const float* sd = sdst + b * NN;
        float ee[MAXD / 32];
        float m = -FLT_MAX;
#pragma unroll
        for (int u = 0; u < MAXD / 32; u++) {
            int k = lane + 32 * u;
            float e = -FLT_MAX;
            if (k < cnt) {
                float v = si + sd[sj[k]];
                e = (v > 0.0f) ? v : ALPHA * v;
            }
            ee[u] = e;
            m = fmaxf(m, e);
        }
#pragma unroll
        for (int off = 16; off > 0; off >>= 1)
            m = fmaxf(m, __shfl_xor_sync(0xffffffffu, m, off));
        float s = 0.0f;
#pragma unroll
        for (int u = 0; u < MAXD / 32; u++) {
            int k = lane + 32 * u;
            if (k < cnt) {
                float w = __expf(ee[u] - m);
                ee[u] = w;
                s += w;
            }
        }
#pragma unroll
        for (int off = 16; off > 0; off >>= 1)
            s += __shfl_xor_sync(0xffffffffu, s, off);
        float inv = 1.0f / s;
#pragma unroll
        for (int u = 0; u < MAXD / 32; u++) {
            int k = lane + 32 * u;
            if (k < cnt) sw[wid][k] = ee[u] * inv;
        }
    }
    __syncthreads();

    // ---- phase 2: fp16 gather-aggregate (__half2 per thread, unroll-4 MLP) ----
    int bb = tid / F2;
    int f2 = tid - bb * F2;
    int b  = b0 + bb;
    const __half2* Hb2 = (const __half2*)H + (size_t)(b * NN) * F2 + f2;
    const float* wrow = sw[bb];

    float ax0 = 0.0f, ay0 = 0.0f, ax1 = 0.0f, ay1 = 0.0f;
    int k = 0;
    for (; k + 4 <= cnt; k += 4) {
        int j0 = sj[k], j1 = sj[k + 1], j2 = sj[k + 2], j3 = sj[k + 3];
        float w0 = wrow[k], w1 = wrow[k + 1], w2 = wrow[k + 2], w3 = wrow[k + 3];
        float2 h0 = __half22float2(Hb2[(size_t)j0 * F2]);
        float2 h1 = __half22float2(Hb2[(size_t)j1 * F2]);
        float2 h2 = __half22float2(Hb2[(size_t)j2 * F2]);
        float2 h3 = __half22float2(Hb2[(size_t)j3 * F2]);
        ax0 = fmaf(w0, h0.x, ax0); ay0 = fmaf(w0, h0.y, ay0);
        ax1 = fmaf(w1, h1.x, ax1); ay1 = fmaf(w1, h1.y, ay1);
        ax0 = fmaf(w2, h2.x, ax0); ay0 = fmaf(w2, h2.y, ay0);
        ax1 = fmaf(w3, h3.x, ax1); ay1 = fmaf(w3, h3.y, ay1);
    }
    for (; k < cnt; k++) {
        float2 h = __half22float2(Hb2[(size_t)sj[k] * F2]);
        ax0 = fmaf(wrow[k], h.x, ax0); ay0 = fmaf(wrow[k], h.y, ay0);
    }
    float accx = ax0 + ax1;
    float accy = ay0 + ay1;

    int base = (b * NN + i) * UU;
    if (LAYER == 1) {
        float gx = 1.0f / (1.0f + __expf(-accx));
        float gy = 1.0f / (1.0f + __expf(-accy));
        if (f2 < UU / 2) {
            // r gate -> r*state (features 2*f2, 2*f2+1 of r)
            const float2 st = ((const float2*)(state + base))[f2];
            float2 rs; rs.x = gx * st.x; rs.y = gy * st.y;
            ((float2*)(g_rs + base))[f2] = rs;
        } else {
            float2 zz; zz.x = gx; zz.y = gy;
            ((float2*)(g_z + base))[f2 - UU / 2] = zz;
        }
    } else {
        float htx = tanhf(accx);
        float hty = tanhf(accy);
        const float2 st = ((const float2*)(state + base))[f2];
        const float2 zz = ((const float2*)(g_z + base))[f2];
        float2 o;
        o.x = fmaf(zz.x, st.x, (1.0f - zz.x) * htx);
        o.y = fmaf(zz.y, st.y, (1.0f - zz.y) * hty);
        ((float2*)(out + base))[f2] = o;
    }
}

// ---------------- launch ----------------
extern "C" void kernel_launch(void* const* d_in, const int* in_sizes, int n_in,
                              void* d_out, int out_size) {
    const float* X     = (const float*)d_in[0];
    const float* state = (const float*)d_in[1];
    const float* adj   = (const float*)d_in[2];
    const float* W1    = (const float*)d_in[3];
    const float* a1    = (const float*)d_in[4];
    const float* W2    = (const float*)d_in[5];
    const float* a2    = (const float*)d_in[6];
    float* out = (float*)d_out;

    // 1) neighbor lists (deterministic)
    build_nbr_kernel<<<NN, 128>>>(adj);

    // 2) layer 1: h1 = [X||state] @ W1  (+ fused scores, fp16 H)
    gemm_cat_kernel<128, 1><<<(BN * NN) / 64, 256>>>(X, state, W1, a1);

    // 3) attention layer 1 (+ sigmoid, r*state, z) — 4 batches/block, 256 thr
    attn_kernel<128, 4, 1><<<dim3(NN, BN / 4), 256>>>(state, out);

    // 4) layer 2: h2 = [X||r*state] @ W2  (+ fused scores, fp16 H)
    gemm_cat_kernel<64, 2><<<(BN * NN) / 64, 256>>>(X, state, W2, a2);

    // 5) attention layer 2 (+ tanh + GRU gate -> out) — 8 batches/block, 256 thr
    attn_kernel<64, 8, 2><<<dim3(NN, BN / 8), 256>>>(state, out);
}